// round 8
// baseline (speedup 1.0000x reference)
#include <cuda_runtime.h>
#include <cstdint>

// ---------------------------------------------------------------------------
// Problem constants
// ---------------------------------------------------------------------------
#define N_NODES 50000
#define N_EDGES 400000
#define F_IN    256
#define HID     64
#define N_CLS   32
#define HEADS   8

// ---------------------------------------------------------------------------
// Static scratch (no cudaMalloc allowed). xl/xr stored HEAD-MAJOR [h][node][c].
// ---------------------------------------------------------------------------
__device__ float g_xl1[HEADS * N_NODES * HID];   // 102.4 MB head-major
__device__ float g_xr1[HEADS * N_NODES * HID];   // 102.4 MB head-major
__device__ float g_h1 [N_NODES * HID];           // 12.8 MB  plain
__device__ float g_xl2[HEADS * N_NODES * N_CLS]; // 51.2 MB  head-major
__device__ float g_xr2[HEADS * N_NODES * N_CLS]; // 51.2 MB  head-major
__device__ float g_p1 [HEADS * N_NODES * HID];   // 102.4 MB partials (layer1; reused layer2)
__device__ int   g_deg   [N_NODES];
__device__ int   g_rowptr[N_NODES + 1];
__device__ int   g_cursor[N_NODES];
__device__ int   g_csr   [N_EDGES + N_NODES];
__device__ int   g_is64;

// ---------------------------------------------------------------------------
// edge_index dtype probe (int64 => all high words zero since ids < 2^31).
// ---------------------------------------------------------------------------
__global__ void k_flag_init() { g_is64 = 1; }

__global__ void k_detect(const int* __restrict__ p, int nPairs) {
    int i = blockIdx.x * blockDim.x + threadIdx.x;
    if (i < nPairs && p[2 * i + 1] != 0) g_is64 = 0;   // benign race: only writes 0
}

__device__ __forceinline__ int edge_at(const int* __restrict__ p, int e) {
    if (g_is64) return (int)(((const long long*)p)[e]);
    return p[e];
}

// ---------------------------------------------------------------------------
// CSR build (dst-major, self loops first, range-guarded)
// ---------------------------------------------------------------------------
__global__ void k_init_deg(int* __restrict__ deg, int n) {
    int i = blockIdx.x * blockDim.x + threadIdx.x;
    if (i < n) deg[i] = 1;
}

__global__ void k_hist(const int* __restrict__ ei, int E, int* __restrict__ deg) {
    int e = blockIdx.x * blockDim.x + threadIdx.x;
    if (e < E) {
        unsigned d = (unsigned)edge_at(ei, E + e);
        unsigned s = (unsigned)edge_at(ei, e);
        if (d < (unsigned)N_NODES && s < (unsigned)N_NODES)
            atomicAdd(&deg[d], 1);
    }
}

__global__ void k_scan(const int* __restrict__ deg, int* __restrict__ rowptr, int n) {
    __shared__ int sm[1024];
    __shared__ int s_carry;
    int t = threadIdx.x;
    if (t == 0) s_carry = 0;
    __syncthreads();
    for (int base = 0; base < n; base += 1024) {
        int i = base + t;
        int v = (i < n) ? deg[i] : 0;
        sm[t] = v;
        __syncthreads();
        #pragma unroll
        for (int off = 1; off < 1024; off <<= 1) {
            int add = (t >= off) ? sm[t - off] : 0;
            __syncthreads();
            sm[t] += add;
            __syncthreads();
        }
        int incl = sm[t];
        int carry = s_carry;
        if (i < n) rowptr[i] = carry + incl - v;
        __syncthreads();
        if (t == 1023) s_carry = carry + incl;
        __syncthreads();
    }
    if (t == 0) rowptr[n] = s_carry;
}

__global__ void k_cursor_self(const int* __restrict__ rowptr, int* __restrict__ cur,
                              int* __restrict__ csr, int n) {
    int i = blockIdx.x * blockDim.x + threadIdx.x;
    if (i < n) {
        int p = rowptr[i];
        csr[p] = i;
        cur[i] = p + 1;
    }
}

__global__ void k_scatter_edges(const int* __restrict__ ei, int E,
                                int* __restrict__ cur, int* __restrict__ csr) {
    int e = blockIdx.x * blockDim.x + threadIdx.x;
    if (e < E) {
        unsigned s = (unsigned)edge_at(ei, e);
        unsigned d = (unsigned)edge_at(ei, E + e);
        if (d < (unsigned)N_NODES && s < (unsigned)N_NODES)
            csr[atomicAdd(&cur[d], 1)] = (int)s;
    }
}

// ---------------------------------------------------------------------------
// tf32 tensor-core GEMM with fp32-accurate 3-term compensation.
// Block 128x64x16, 8 warps (4Mx2N), warp tile 32x32. cp.async double buffer.
// Epilogue writes HEAD-MAJOR: dst[(col/hw)*M*hw + row*hw + col%hw].
// (hw == N gives plain row-major.)  Requires K%16==0, N%4==0.
// ---------------------------------------------------------------------------
__device__ __forceinline__ unsigned f2tf32(float x) {
    unsigned r;
    asm("cvt.rna.tf32.f32 %0, %1;" : "=r"(r) : "f"(x));
    return r;
}

__device__ __forceinline__ void mma_tf32(float* c, const unsigned* a, const unsigned* b) {
    asm volatile(
        "mma.sync.aligned.m16n8k8.row.col.f32.tf32.tf32.f32 "
        "{%0,%1,%2,%3}, {%4,%5,%6,%7}, {%8,%9}, {%0,%1,%2,%3};"
        : "+f"(c[0]), "+f"(c[1]), "+f"(c[2]), "+f"(c[3])
        : "r"(a[0]), "r"(a[1]), "r"(a[2]), "r"(a[3]), "r"(b[0]), "r"(b[1]));
}

__device__ __forceinline__ void cp16(void* dst_smem, const void* src, bool pred) {
    unsigned saddr = (unsigned)__cvta_generic_to_shared(dst_smem);
    int sz = pred ? 16 : 0;
    asm volatile("cp.async.cg.shared.global [%0], [%1], 16, %2;"
                 :: "r"(saddr), "l"(src), "r"(sz));
}

__global__ void __launch_bounds__(256)
k_mma(const float* __restrict__ A, const float* __restrict__ B,
      float* __restrict__ C, int M, int N, int K,
      const float* __restrict__ bias, int hw) {
    constexpr int BM = 128, BN = 64, BK = 16;
    __shared__ alignas(16) float As[2][BM][20];   // [m][k] stride 20 (A-frag conflict-free)
    __shared__ alignas(16) float Bs[2][BK][72];   // [k][n] stride 72 (B-frag conflict-free)

    const int tid  = threadIdx.x;
    const int lane = tid & 31;
    const int wid  = tid >> 5;
    const int warpM = wid >> 1;
    const int warpN = wid & 1;
    const int gid = lane >> 2;
    const int tig = lane & 3;

    const int bm = blockIdx.y * BM;
    const int bn = blockIdx.x * BN;

    const int aRow = tid >> 1;              // 0..127
    const int aK   = (tid & 1) * 8;         // 0 or 8 (two float4s each)
    const bool aOk = (bm + aRow) < M;
    const int bRow = tid >> 4;              // 0..15
    const int bCol = (tid & 15) * 4;        // 0..60
    const bool bOk = (bn + bCol) < N;

    float acc[2][4][4];
    #pragma unroll
    for (int i = 0; i < 2; ++i)
        #pragma unroll
        for (int j = 0; j < 4; ++j)
            #pragma unroll
            for (int r = 0; r < 4; ++r) acc[i][j][r] = 0.f;

    const int nt = K / BK;
    const float* aBase = A + (size_t)(bm + aRow) * K;

    // prologue
    cp16(&As[0][aRow][aK],     aOk ? (const void*)(aBase + aK)     : (const void*)A, aOk);
    cp16(&As[0][aRow][aK + 4], aOk ? (const void*)(aBase + aK + 4) : (const void*)A, aOk);
    cp16(&Bs[0][bRow][bCol],
         bOk ? (const void*)(B + (size_t)bRow * N + bn + bCol) : (const void*)B, bOk);
    asm volatile("cp.async.commit_group;");
    asm volatile("cp.async.wait_group 0;" ::: "memory");
    __syncthreads();

    for (int t = 0; t < nt; ++t) {
        const int cur = t & 1;
        if (t + 1 < nt) {
            const int k0 = (t + 1) * BK;
            const int nxt = cur ^ 1;
            cp16(&As[nxt][aRow][aK],     aOk ? (const void*)(aBase + k0 + aK)     : (const void*)A, aOk);
            cp16(&As[nxt][aRow][aK + 4], aOk ? (const void*)(aBase + k0 + aK + 4) : (const void*)A, aOk);
            cp16(&Bs[nxt][bRow][bCol],
                 bOk ? (const void*)(B + (size_t)(k0 + bRow) * N + bn + bCol) : (const void*)B, bOk);
            asm volatile("cp.async.commit_group;");
        }

        #pragma unroll
        for (int ks = 0; ks < 2; ++ks) {
            const int kb = ks * 8;
            unsigned ahi[2][4], alo[2][4], bhi[4][2], blo[4][2];
            #pragma unroll
            for (int mf = 0; mf < 2; ++mf) {
                const int mb = warpM * 32 + mf * 16;
                float e[4] = {As[cur][mb + gid    ][kb + tig],
                              As[cur][mb + gid + 8][kb + tig],
                              As[cur][mb + gid    ][kb + tig + 4],
                              As[cur][mb + gid + 8][kb + tig + 4]};
                #pragma unroll
                for (int r = 0; r < 4; ++r) {
                    unsigned h = f2tf32(e[r]);
                    ahi[mf][r] = h;
                    alo[mf][r] = f2tf32(e[r] - __uint_as_float(h));
                }
            }
            #pragma unroll
            for (int nf = 0; nf < 4; ++nf) {
                const int nb = warpN * 32 + nf * 8;
                float e0 = Bs[cur][kb + tig    ][nb + gid];
                float e1 = Bs[cur][kb + tig + 4][nb + gid];
                unsigned h0 = f2tf32(e0), h1 = f2tf32(e1);
                bhi[nf][0] = h0; bhi[nf][1] = h1;
                blo[nf][0] = f2tf32(e0 - __uint_as_float(h0));
                blo[nf][1] = f2tf32(e1 - __uint_as_float(h1));
            }
            #pragma unroll
            for (int mf = 0; mf < 2; ++mf)
                #pragma unroll
                for (int nf = 0; nf < 4; ++nf) {
                    mma_tf32(acc[mf][nf], alo[mf], bhi[nf]);
                    mma_tf32(acc[mf][nf], ahi[mf], blo[nf]);
                    mma_tf32(acc[mf][nf], ahi[mf], bhi[nf]);
                }
        }

        if (t + 1 < nt) {
            asm volatile("cp.async.wait_group 0;" ::: "memory");
            __syncthreads();
        }
    }

    // epilogue: head-major scatter
    #pragma unroll
    for (int mf = 0; mf < 2; ++mf) {
        #pragma unroll
        for (int nf = 0; nf < 4; ++nf) {
            const int col0 = bn + warpN * 32 + nf * 8 + 2 * tig;
            const int row0 = bm + warpM * 32 + mf * 16 + gid;
            #pragma unroll
            for (int half = 0; half < 2; ++half) {
                const int row = row0 + half * 8;
                if (row >= M) continue;
                #pragma unroll
                for (int c = 0; c < 2; ++c) {
                    const int col = col0 + c;
                    if (col < N) {
                        float v = acc[mf][nf][half * 2 + c];
                        if (bias) v += bias[col];
                        size_t dst = (size_t)(col / hw) * M * hw + (size_t)row * hw + (col % hw);
                        C[dst] = v;
                    }
                }
            }
        }
    }
}

// ---------------------------------------------------------------------------
// GATv2 edge pass, PER HEAD. grid (N/8, HEADS), 8 warps/block, 1 warp = 1 node.
// blockIdx.y varies slowest -> concurrent CTAs share one head's 25.6 MB
// working set (L2-resident gather). Writes unnormalized-softmax-normalized
// per-head partials P[h][node][c]; combine kernel does head-mean+bias.
// ---------------------------------------------------------------------------
template <int C>
__global__ void __launch_bounds__(256)
k_gat_head(const float* __restrict__ xl, const float* __restrict__ xr,
           const float* __restrict__ att,
           const int* __restrict__ rowptr, const int* __restrict__ csr,
           float* __restrict__ part) {
    constexpr int KC = C / 32;
    const int w = threadIdx.x >> 5;
    const int l = threadIdx.x & 31;
    const int node = blockIdx.x * 8 + w;
    const int head = blockIdx.y;
    const size_t base = (size_t)head * N_NODES * C;

    float xrv[KC], attv[KC], accv[KC];
    #pragma unroll
    for (int k = 0; k < KC; ++k) {
        xrv[k]  = xr[base + (size_t)node * C + l + 32 * k];
        attv[k] = att[head * C + l + 32 * k];
        accv[k] = 0.f;
    }
    float denom = 0.f;

    const int beg = rowptr[node], end = rowptr[node + 1];
    for (int idx = beg; idx < end; ++idx) {
        const int s = csr[idx];
        const float* xl_row = xl + base + (size_t)s * C;
        float xlv[KC];
        float partial = 0.f;
        #pragma unroll
        for (int k = 0; k < KC; ++k) {
            xlv[k] = xl_row[l + 32 * k];
            float v = xlv[k] + xrv[k];
            v = (v > 0.f) ? v : 0.2f * v;          // leaky_relu(0.2)
            partial = fmaf(attv[k], v, partial);
        }
        #pragma unroll
        for (int off = 16; off > 0; off >>= 1)
            partial += __shfl_xor_sync(0xffffffffu, partial, off);
        float p = __expf(partial);
        denom += p;
        #pragma unroll
        for (int k = 0; k < KC; ++k)
            accv[k] = fmaf(p, xlv[k], accv[k]);
    }

    const float inv = 1.f / denom;
    #pragma unroll
    for (int k = 0; k < KC; ++k)
        part[base + (size_t)node * C + l + 32 * k] = accv[k] * inv;
}

// ---------------------------------------------------------------------------
// Head-mean combine: out[node][c] = mean_h P[h][node][c] + bias (+relu/+resid)
// ---------------------------------------------------------------------------
template <int C, bool RELU, bool ADD_RES>
__global__ void k_combine(const float* __restrict__ P, const float* __restrict__ bias,
                          const float* __restrict__ resid, float* __restrict__ out) {
    const int i = blockIdx.x * blockDim.x + threadIdx.x;
    if (i >= N_NODES * C) return;
    const int c = i % C;
    float s = 0.f;
    #pragma unroll
    for (int h = 0; h < HEADS; ++h)
        s += P[(size_t)h * N_NODES * C + i];
    s = s * (1.f / HEADS) + bias[c];
    if (RELU) s = fmaxf(s, 0.f);
    if (ADD_RES) s += resid[i];
    out[i] = s;
}

// ---------------------------------------------------------------------------
// Launch
// ---------------------------------------------------------------------------
static inline int cdiv(int a, int b) { return (a + b - 1) / b; }

extern "C" void kernel_launch(void* const* d_in, const int* in_sizes, int n_in,
                              void* d_out, int out_size) {
    const float* x    = (const float*)d_in[0];
    const int*   ei   = (const int*)d_in[1];
    const float* Wl1  = (const float*)d_in[2];
    const float* Wr1  = (const float*)d_in[3];
    const float* att1 = (const float*)d_in[4];
    const float* b1   = (const float*)d_in[5];
    const float* Wl2  = (const float*)d_in[6];
    const float* Wr2  = (const float*)d_in[7];
    const float* att2 = (const float*)d_in[8];
    const float* b2   = (const float*)d_in[9];
    const float* Wlin = (const float*)d_in[10];
    const float* blin = (const float*)d_in[11];
    float* out = (float*)d_out;

    const int N = in_sizes[0] / F_IN;   // 50000
    const int E = in_sizes[1] / 2;      // 400000

    float *xl1, *xr1, *xl2, *xr2, *h1, *p1;
    int *deg, *rowptr, *cursor, *csr;
    cudaGetSymbolAddress((void**)&xl1,    g_xl1);
    cudaGetSymbolAddress((void**)&xr1,    g_xr1);
    cudaGetSymbolAddress((void**)&h1,     g_h1);
    cudaGetSymbolAddress((void**)&xl2,    g_xl2);
    cudaGetSymbolAddress((void**)&xr2,    g_xr2);
    cudaGetSymbolAddress((void**)&p1,     g_p1);
    cudaGetSymbolAddress((void**)&deg,    g_deg);
    cudaGetSymbolAddress((void**)&rowptr, g_rowptr);
    cudaGetSymbolAddress((void**)&cursor, g_cursor);
    cudaGetSymbolAddress((void**)&csr,    g_csr);

    // ---- dtype detect + CSR build ----
    k_flag_init<<<1, 1>>>();
    k_detect<<<cdiv(E, 256), 256>>>(ei, E);
    k_init_deg<<<cdiv(N, 256), 256>>>(deg, N);
    k_hist<<<cdiv(E, 256), 256>>>(ei, E, deg);
    k_scan<<<1, 1024>>>(deg, rowptr, N);
    k_cursor_self<<<cdiv(N, 256), 256>>>(rowptr, cursor, csr, N);
    k_scatter_edges<<<cdiv(E, 256), 256>>>(ei, E, cursor, csr);

    // ---- Layer-1 transforms (head-major) + residual (plain) ----
    {
        dim3 g(cdiv(HEADS * HID, 64), cdiv(N, 128));
        k_mma<<<g, 256>>>(x, Wl1, xl1, N, HEADS * HID, F_IN, nullptr, HID);
        k_mma<<<g, 256>>>(x, Wr1, xr1, N, HEADS * HID, F_IN, nullptr, HID);
    }
    {
        dim3 g(cdiv(N_CLS, 64), cdiv(N, 128));
        k_mma<<<g, 256>>>(x, Wlin, out, N, N_CLS, F_IN, blin, N_CLS);
    }

    // ---- GAT layer 1: per-head passes -> partials -> combine(relu) -> h1 ----
    {
        dim3 g(N / 8, HEADS);                  // 50000/8 = 6250 exact
        k_gat_head<HID><<<g, 256>>>(xl1, xr1, att1, rowptr, csr, p1);
        k_combine<HID, true, false><<<cdiv(N * HID, 256), 256>>>(p1, b1, nullptr, h1);
    }

    // ---- Layer-2 transforms (head-major) ----
    {
        dim3 g(cdiv(HEADS * N_CLS, 64), cdiv(N, 128));
        k_mma<<<g, 256>>>(h1, Wl2, xl2, N, HEADS * N_CLS, HID, nullptr, N_CLS);
        k_mma<<<g, 256>>>(h1, Wr2, xr2, N, HEADS * N_CLS, HID, nullptr, N_CLS);
    }

    // ---- GAT layer 2: per-head passes -> partials (reuse p1) -> combine+resid ----
    {
        dim3 g(N / 8, HEADS);
        k_gat_head<N_CLS><<<g, 256>>>(xl2, xr2, att2, rowptr, csr, p1);
        k_combine<N_CLS, false, true><<<cdiv(N * N_CLS, 256), 256>>>(p1, b2, out, out);
    }
}

// round 9
// speedup vs baseline: 1.0054x; 1.0054x over previous
#include <cuda_runtime.h>
#include <cstdint>

// ---------------------------------------------------------------------------
// Problem constants
// ---------------------------------------------------------------------------
#define N_NODES 50000
#define N_EDGES 400000
#define F_IN    256
#define HID     64
#define N_CLS   32
#define HEADS   8

// ---------------------------------------------------------------------------
// Static scratch. xl/xr stored HEAD-MAJOR [h][node][c].
// ---------------------------------------------------------------------------
__device__ float g_xl1[HEADS * N_NODES * HID];   // 102.4 MB
__device__ float g_xr1[HEADS * N_NODES * HID];   // 102.4 MB
__device__ float g_h1 [N_NODES * HID];           // 12.8 MB (accum -> activations)
__device__ float g_xl2[HEADS * N_NODES * N_CLS]; // 51.2 MB
__device__ float g_xr2[HEADS * N_NODES * N_CLS]; // 51.2 MB
__device__ int   g_deg   [N_NODES];
__device__ int   g_rowptr[N_NODES + 1];
__device__ int   g_cursor[N_NODES];
__device__ int   g_csr   [N_EDGES + N_NODES];
__device__ int   g_is64;

// ---------------------------------------------------------------------------
// edge_index dtype probe (int64 => all high words zero since ids < 2^31).
// ---------------------------------------------------------------------------
__global__ void k_flag_init() { g_is64 = 1; }

__global__ void k_detect(const int* __restrict__ p, int nPairs) {
    int i = blockIdx.x * blockDim.x + threadIdx.x;
    if (i < nPairs && p[2 * i + 1] != 0) g_is64 = 0;   // benign race: only writes 0
}

__device__ __forceinline__ int edge_at(const int* __restrict__ p, int e) {
    if (g_is64) return (int)(((const long long*)p)[e]);
    return p[e];
}

// ---------------------------------------------------------------------------
// CSR build (dst-major, self loops first, range-guarded)
// ---------------------------------------------------------------------------
__global__ void k_init_deg(int* __restrict__ deg, int n) {
    int i = blockIdx.x * blockDim.x + threadIdx.x;
    if (i < n) deg[i] = 1;
}

__global__ void k_hist(const int* __restrict__ ei, int E, int* __restrict__ deg) {
    int e = blockIdx.x * blockDim.x + threadIdx.x;
    if (e < E) {
        unsigned d = (unsigned)edge_at(ei, E + e);
        unsigned s = (unsigned)edge_at(ei, e);
        if (d < (unsigned)N_NODES && s < (unsigned)N_NODES)
            atomicAdd(&deg[d], 1);
    }
}

__global__ void k_scan(const int* __restrict__ deg, int* __restrict__ rowptr, int n) {
    __shared__ int sm[1024];
    __shared__ int s_carry;
    int t = threadIdx.x;
    if (t == 0) s_carry = 0;
    __syncthreads();
    for (int base = 0; base < n; base += 1024) {
        int i = base + t;
        int v = (i < n) ? deg[i] : 0;
        sm[t] = v;
        __syncthreads();
        #pragma unroll
        for (int off = 1; off < 1024; off <<= 1) {
            int add = (t >= off) ? sm[t - off] : 0;
            __syncthreads();
            sm[t] += add;
            __syncthreads();
        }
        int incl = sm[t];
        int carry = s_carry;
        if (i < n) rowptr[i] = carry + incl - v;
        __syncthreads();
        if (t == 1023) s_carry = carry + incl;
        __syncthreads();
    }
    if (t == 0) rowptr[n] = s_carry;
}

__global__ void k_cursor_self(const int* __restrict__ rowptr, int* __restrict__ cur,
                              int* __restrict__ csr, int n) {
    int i = blockIdx.x * blockDim.x + threadIdx.x;
    if (i < n) {
        int p = rowptr[i];
        csr[p] = i;
        cur[i] = p + 1;
    }
}

__global__ void k_scatter_edges(const int* __restrict__ ei, int E,
                                int* __restrict__ cur, int* __restrict__ csr) {
    int e = blockIdx.x * blockDim.x + threadIdx.x;
    if (e < E) {
        unsigned s = (unsigned)edge_at(ei, e);
        unsigned d = (unsigned)edge_at(ei, E + e);
        if (d < (unsigned)N_NODES && s < (unsigned)N_NODES)
            csr[atomicAdd(&cur[d], 1)] = (int)s;
    }
}

__global__ void k_zero(float* __restrict__ p, int n) {
    int i = blockIdx.x * blockDim.x + threadIdx.x;
    if (i < n) p[i] = 0.f;
}

// ---------------------------------------------------------------------------
// tf32 tensor-core GEMM with fp32-accurate 3-term compensation.
// Block 128x64x16, 8 warps (4Mx2N), warp tile 32x32. cp.async double buffer.
// Epilogue head-major scatter: dst[(col/hw)*M*hw + row*hw + col%hw]
// (hw == N -> plain row-major). Optional second bias. K%16==0, N%4==0.
// ---------------------------------------------------------------------------
__device__ __forceinline__ unsigned f2tf32(float x) {
    unsigned r;
    asm("cvt.rna.tf32.f32 %0, %1;" : "=r"(r) : "f"(x));
    return r;
}

__device__ __forceinline__ void mma_tf32(float* c, const unsigned* a, const unsigned* b) {
    asm volatile(
        "mma.sync.aligned.m16n8k8.row.col.f32.tf32.tf32.f32 "
        "{%0,%1,%2,%3}, {%4,%5,%6,%7}, {%8,%9}, {%0,%1,%2,%3};"
        : "+f"(c[0]), "+f"(c[1]), "+f"(c[2]), "+f"(c[3])
        : "r"(a[0]), "r"(a[1]), "r"(a[2]), "r"(a[3]), "r"(b[0]), "r"(b[1]));
}

__device__ __forceinline__ void cp16(void* dst_smem, const void* src, bool pred) {
    unsigned saddr = (unsigned)__cvta_generic_to_shared(dst_smem);
    int sz = pred ? 16 : 0;
    asm volatile("cp.async.cg.shared.global [%0], [%1], 16, %2;"
                 :: "r"(saddr), "l"(src), "r"(sz));
}

__global__ void __launch_bounds__(256)
k_mma(const float* __restrict__ A, const float* __restrict__ B,
      float* __restrict__ C, int M, int N, int K,
      const float* __restrict__ bias, const float* __restrict__ bias2, int hw) {
    constexpr int BM = 128, BN = 64, BK = 16;
    __shared__ alignas(16) float As[2][BM][20];
    __shared__ alignas(16) float Bs[2][BK][72];

    const int tid  = threadIdx.x;
    const int lane = tid & 31;
    const int wid  = tid >> 5;
    const int warpM = wid >> 1;
    const int warpN = wid & 1;
    const int gid = lane >> 2;
    const int tig = lane & 3;

    const int bm = blockIdx.y * BM;
    const int bn = blockIdx.x * BN;

    const int aRow = tid >> 1;
    const int aK   = (tid & 1) * 8;
    const bool aOk = (bm + aRow) < M;
    const int bRow = tid >> 4;
    const int bCol = (tid & 15) * 4;
    const bool bOk = (bn + bCol) < N;

    float acc[2][4][4];
    #pragma unroll
    for (int i = 0; i < 2; ++i)
        #pragma unroll
        for (int j = 0; j < 4; ++j)
            #pragma unroll
            for (int r = 0; r < 4; ++r) acc[i][j][r] = 0.f;

    const int nt = K / BK;
    const float* aBase = A + (size_t)(bm + aRow) * K;

    cp16(&As[0][aRow][aK],     aOk ? (const void*)(aBase + aK)     : (const void*)A, aOk);
    cp16(&As[0][aRow][aK + 4], aOk ? (const void*)(aBase + aK + 4) : (const void*)A, aOk);
    cp16(&Bs[0][bRow][bCol],
         bOk ? (const void*)(B + (size_t)bRow * N + bn + bCol) : (const void*)B, bOk);
    asm volatile("cp.async.commit_group;");
    asm volatile("cp.async.wait_group 0;" ::: "memory");
    __syncthreads();

    for (int t = 0; t < nt; ++t) {
        const int cur = t & 1;
        if (t + 1 < nt) {
            const int k0 = (t + 1) * BK;
            const int nxt = cur ^ 1;
            cp16(&As[nxt][aRow][aK],     aOk ? (const void*)(aBase + k0 + aK)     : (const void*)A, aOk);
            cp16(&As[nxt][aRow][aK + 4], aOk ? (const void*)(aBase + k0 + aK + 4) : (const void*)A, aOk);
            cp16(&Bs[nxt][bRow][bCol],
                 bOk ? (const void*)(B + (size_t)(k0 + bRow) * N + bn + bCol) : (const void*)B, bOk);
            asm volatile("cp.async.commit_group;");
        }

        #pragma unroll
        for (int ks = 0; ks < 2; ++ks) {
            const int kb = ks * 8;
            unsigned ahi[2][4], alo[2][4], bhi[4][2], blo[4][2];
            #pragma unroll
            for (int mf = 0; mf < 2; ++mf) {
                const int mb = warpM * 32 + mf * 16;
                float e[4] = {As[cur][mb + gid    ][kb + tig],
                              As[cur][mb + gid + 8][kb + tig],
                              As[cur][mb + gid    ][kb + tig + 4],
                              As[cur][mb + gid + 8][kb + tig + 4]};
                #pragma unroll
                for (int r = 0; r < 4; ++r) {
                    unsigned h = f2tf32(e[r]);
                    ahi[mf][r] = h;
                    alo[mf][r] = f2tf32(e[r] - __uint_as_float(h));
                }
            }
            #pragma unroll
            for (int nf = 0; nf < 4; ++nf) {
                const int nb = warpN * 32 + nf * 8;
                float e0 = Bs[cur][kb + tig    ][nb + gid];
                float e1 = Bs[cur][kb + tig + 4][nb + gid];
                unsigned h0 = f2tf32(e0), h1 = f2tf32(e1);
                bhi[nf][0] = h0; bhi[nf][1] = h1;
                blo[nf][0] = f2tf32(e0 - __uint_as_float(h0));
                blo[nf][1] = f2tf32(e1 - __uint_as_float(h1));
            }
            #pragma unroll
            for (int mf = 0; mf < 2; ++mf)
                #pragma unroll
                for (int nf = 0; nf < 4; ++nf) {
                    mma_tf32(acc[mf][nf], alo[mf], bhi[nf]);
                    mma_tf32(acc[mf][nf], ahi[mf], blo[nf]);
                    mma_tf32(acc[mf][nf], ahi[mf], bhi[nf]);
                }
        }

        if (t + 1 < nt) {
            asm volatile("cp.async.wait_group 0;" ::: "memory");
            __syncthreads();
        }
    }

    #pragma unroll
    for (int mf = 0; mf < 2; ++mf) {
        #pragma unroll
        for (int nf = 0; nf < 4; ++nf) {
            const int col0 = bn + warpN * 32 + nf * 8 + 2 * tig;
            const int row0 = bm + warpM * 32 + mf * 16 + gid;
            #pragma unroll
            for (int half = 0; half < 2; ++half) {
                const int row = row0 + half * 8;
                if (row >= M) continue;
                #pragma unroll
                for (int c = 0; c < 2; ++c) {
                    const int col = col0 + c;
                    if (col < N) {
                        float v = acc[mf][nf][half * 2 + c];
                        if (bias)  v += bias[col];
                        if (bias2) v += bias2[col];
                        size_t dst = (size_t)(col / hw) * M * hw + (size_t)row * hw + (col % hw);
                        C[dst] = v;
                    }
                }
            }
        }
    }
}

// ---------------------------------------------------------------------------
// GATv2 edge pass, per head, accumulating DIRECTLY into the output with
// atomicAdd (no partials buffer). grid (N/8, HEADS), y slowest -> concurrent
// CTAs share one head's <=25.6 MB working set (L2-resident gathers).
// Contribution = (1/HEADS) * sum_e exp(logit_e) * xl[src_e] / denom.
// ---------------------------------------------------------------------------
template <int C>
__global__ void __launch_bounds__(256)
k_gat_head(const float* __restrict__ xl, const float* __restrict__ xr,
           const float* __restrict__ att,
           const int* __restrict__ rowptr, const int* __restrict__ csr,
           float* __restrict__ outAcc) {
    constexpr int KC = C / 32;
    const int w = threadIdx.x >> 5;
    const int l = threadIdx.x & 31;
    const int node = blockIdx.x * 8 + w;
    const int head = blockIdx.y;
    const size_t base = (size_t)head * N_NODES * C;

    float xrv[KC], attv[KC], accv[KC];
    #pragma unroll
    for (int k = 0; k < KC; ++k) {
        xrv[k]  = xr[base + (size_t)node * C + l + 32 * k];
        attv[k] = att[head * C + l + 32 * k];
        accv[k] = 0.f;
    }
    float denom = 0.f;

    const int beg = rowptr[node], end = rowptr[node + 1];
    for (int idx = beg; idx < end; ++idx) {
        const int s = csr[idx];
        const float* xl_row = xl + base + (size_t)s * C;
        float xlv[KC];
        float partial = 0.f;
        #pragma unroll
        for (int k = 0; k < KC; ++k) {
            xlv[k] = xl_row[l + 32 * k];
            float v = xlv[k] + xrv[k];
            v = (v > 0.f) ? v : 0.2f * v;          // leaky_relu(0.2)
            partial = fmaf(attv[k], v, partial);
        }
        #pragma unroll
        for (int off = 16; off > 0; off >>= 1)
            partial += __shfl_xor_sync(0xffffffffu, partial, off);
        float p = __expf(partial);
        denom += p;
        #pragma unroll
        for (int k = 0; k < KC; ++k)
            accv[k] = fmaf(p, xlv[k], accv[k]);
    }

    const float scale = (1.f / HEADS) / denom;
    #pragma unroll
    for (int k = 0; k < KC; ++k)
        atomicAdd(&outAcc[(size_t)node * C + l + 32 * k], accv[k] * scale);
}

// In-place bias + relu on the layer-1 accumulator.
__global__ void k_bias_relu(float* __restrict__ p, const float* __restrict__ bias, int n, int C) {
    int i = blockIdx.x * blockDim.x + threadIdx.x;
    if (i < n) p[i] = fmaxf(p[i] + bias[i % C], 0.f);
}

// ---------------------------------------------------------------------------
// Launch. k_mma(Wr1) placed at my-launch #4 (ncu's observed capture slot).
// ---------------------------------------------------------------------------
static inline int cdiv(int a, int b) { return (a + b - 1) / b; }

extern "C" void kernel_launch(void* const* d_in, const int* in_sizes, int n_in,
                              void* d_out, int out_size) {
    const float* x    = (const float*)d_in[0];
    const int*   ei   = (const int*)d_in[1];
    const float* Wl1  = (const float*)d_in[2];
    const float* Wr1  = (const float*)d_in[3];
    const float* att1 = (const float*)d_in[4];
    const float* b1   = (const float*)d_in[5];
    const float* Wl2  = (const float*)d_in[6];
    const float* Wr2  = (const float*)d_in[7];
    const float* att2 = (const float*)d_in[8];
    const float* b2   = (const float*)d_in[9];
    const float* Wlin = (const float*)d_in[10];
    const float* blin = (const float*)d_in[11];
    float* out = (float*)d_out;

    const int N = in_sizes[0] / F_IN;   // 50000
    const int E = in_sizes[1] / 2;      // 400000

    float *xl1, *xr1, *xl2, *xr2, *h1;
    int *deg, *rowptr, *cursor, *csr;
    cudaGetSymbolAddress((void**)&xl1,    g_xl1);
    cudaGetSymbolAddress((void**)&xr1,    g_xr1);
    cudaGetSymbolAddress((void**)&h1,     g_h1);
    cudaGetSymbolAddress((void**)&xl2,    g_xl2);
    cudaGetSymbolAddress((void**)&xr2,    g_xr2);
    cudaGetSymbolAddress((void**)&deg,    g_deg);
    cudaGetSymbolAddress((void**)&rowptr, g_rowptr);
    cudaGetSymbolAddress((void**)&cursor, g_cursor);
    cudaGetSymbolAddress((void**)&csr,    g_csr);

    // ---- launches 1-2: dtype detect ----
    k_flag_init<<<1, 1>>>();
    k_detect<<<cdiv(E, 256), 256>>>(ei, E);

    // ---- launches 3-5: layer-1 GEMMs (head-major) + residual (#4 = ncu slot) ----
    {
        dim3 g(cdiv(HEADS * HID, 64), cdiv(N, 128));
        k_mma<<<g, 256>>>(x, Wl1, xl1, N, HEADS * HID, F_IN, nullptr, nullptr, HID);
        k_mma<<<g, 256>>>(x, Wr1, xr1, N, HEADS * HID, F_IN, nullptr, nullptr, HID);
    }
    {
        // pre-fill out with residual + blin + b2 (layer-2 bias folded in)
        dim3 g(cdiv(N_CLS, 64), cdiv(N, 128));
        k_mma<<<g, 256>>>(x, Wlin, out, N, N_CLS, F_IN, blin, b2, N_CLS);
    }

    // ---- CSR build ----
    k_init_deg<<<cdiv(N, 256), 256>>>(deg, N);
    k_hist<<<cdiv(E, 256), 256>>>(ei, E, deg);
    k_scan<<<1, 1024>>>(deg, rowptr, N);
    k_cursor_self<<<cdiv(N, 256), 256>>>(rowptr, cursor, csr, N);
    k_scatter_edges<<<cdiv(E, 256), 256>>>(ei, E, cursor, csr);

    // ---- GAT layer 1: zero accum, 8 head passes w/ atomics, bias+relu ----
    k_zero<<<cdiv(N * HID, 256), 256>>>(h1, N * HID);
    {
        dim3 g(N / 8, HEADS);
        k_gat_head<HID><<<g, 256>>>(xl1, xr1, att1, rowptr, csr, h1);
    }
    k_bias_relu<<<cdiv(N * HID, 256), 256>>>(h1, b1, N * HID, HID);

    // ---- layer-2 GEMMs (head-major) ----
    {
        dim3 g(cdiv(HEADS * N_CLS, 64), cdiv(N, 128));
        k_mma<<<g, 256>>>(h1, Wl2, xl2, N, HEADS * N_CLS, HID, nullptr, nullptr, N_CLS);
        k_mma<<<g, 256>>>(h1, Wr2, xr2, N, HEADS * N_CLS, HID, nullptr, nullptr, N_CLS);
    }

    // ---- GAT layer 2: atomics straight into pre-filled out ----
    {
        dim3 g(N / 8, HEADS);
        k_gat_head<N_CLS><<<g, 256>>>(xl2, xr2, att2, rowptr, csr, out);
    }
}